// round 5
// baseline (speedup 1.0000x reference)
#include <cuda_runtime.h>

// PixelWiseNet: out[h,w] = bias + sum_{c,k} p_a[c,k] * relu(x[c,h,w]*rowsum(M[c]) + bias_c[c] - p_t[c,k])
// C=3, H=W=1024, K=16. Output [1024,1024] f32.
//
// Algebra:  a*relu(s-t) = a*max(s,t) - a*t
//           a*max(x*scale+bc, t) = (a*|scale|)*max(x*sgn, (t-bc)/|scale|) + a*bc
// => out = CONST + sum_{c,k} a'_{ck} * max(u_c, t'_{ck}),  u_c = x_c * sgn(scale_c)
//    CONST = bias + sum_{c,k} a_{ck}*(bc_c - t_{ck})
// Per pixel: 48 FMNMX (alu) + 48 FFMA (fma) + 3 FMUL.
//
// R3: occupancy fix. 1 float4/thread -> 262144 threads (one full wave,
// ~56 warps/SM), dual accumulators for 8 independent FMA chains/thread.

#define C 3
#define K 16
#define HW (1024 * 1024)
#define N4 (HW / 4)              // float4 per channel plane = 262144
#define THREADS 256
#define BLOCKS (N4 / THREADS)    // 1024

__global__ __launch_bounds__(THREADS, 7)
void pixelwise_kernel(const float4* __restrict__ x,
                      const float* __restrict__ M,
                      const float* __restrict__ p_a,
                      const float* __restrict__ p_t,
                      const float* __restrict__ bias_c,
                      const float* __restrict__ bias,
                      float4* __restrict__ out) {
    __shared__ float2 sh_at[C * K];   // (a', t') -> one LDS.64 per hinge
    __shared__ float  sh_xsign[C];
    __shared__ float  sh_const;
    __shared__ float  sh_partial[64];

    int tid = threadIdx.x;

    // ---- per-block parameter transform (48 threads, overlapped across blocks) ----
    if (tid < C * K) {
        int c = tid / K;
        float scale = M[c * 3 + 0] + M[c * 3 + 1] + M[c * 3 + 2];
        float sa = fabsf(scale);
        float a = p_a[tid], t = p_t[tid], bc = bias_c[c];
        float ap, tp, cst;
        if (sa > 0.0f) {
            ap  = a * sa;
            tp  = (t - bc) / sa;
            cst = a * (bc - t);
        } else {
            ap = 0.0f; tp = 0.0f;
            cst = a * (fmaxf(bc, t) - t);
        }
        sh_at[tid] = make_float2(ap, tp);
        sh_partial[tid] = cst;
        if (tid < C) sh_xsign[tid] = (scale >= 0.0f) ? 1.0f : -1.0f;
    } else if (tid < 64) {
        sh_partial[tid] = 0.0f;
    }
    __syncthreads();
    if (tid < 32) {
        float v = sh_partial[tid] + sh_partial[tid + 32];
        #pragma unroll
        for (int o = 16; o; o >>= 1) v += __shfl_xor_sync(0xffffffffu, v, o);
        if (tid == 0) sh_const = v + bias[0];
    }
    __syncthreads();

    // ---- main: 4 pixels (1 float4) per thread, 2 accumulators per pixel ----
    int i = blockIdx.x * THREADS + tid;
    float b = sh_const;
    float4 accA = make_float4(b, b, b, b);          // even hinges + CONST
    float4 accB = make_float4(0.f, 0.f, 0.f, 0.f);  // odd hinges

    #pragma unroll
    for (int c = 0; c < C; c++) {
        float xs = sh_xsign[c];
        float4 v = x[c * N4 + i];
        float ux = v.x * xs, uy = v.y * xs, uz = v.z * xs, uw = v.w * xs;
        #pragma unroll
        for (int k = 0; k < K; k += 2) {
            float2 p0 = sh_at[c * K + k];
            float2 p1 = sh_at[c * K + k + 1];
            accA.x = fmaf(p0.x, fmaxf(ux, p0.y), accA.x);
            accA.y = fmaf(p0.x, fmaxf(uy, p0.y), accA.y);
            accA.z = fmaf(p0.x, fmaxf(uz, p0.y), accA.z);
            accA.w = fmaf(p0.x, fmaxf(uw, p0.y), accA.w);
            accB.x = fmaf(p1.x, fmaxf(ux, p1.y), accB.x);
            accB.y = fmaf(p1.x, fmaxf(uy, p1.y), accB.y);
            accB.z = fmaf(p1.x, fmaxf(uz, p1.y), accB.z);
            accB.w = fmaf(p1.x, fmaxf(uw, p1.y), accB.w);
        }
    }

    float4 r;
    r.x = accA.x + accB.x;
    r.y = accA.y + accB.y;
    r.z = accA.z + accB.z;
    r.w = accA.w + accB.w;
    out[i] = r;
}

extern "C" void kernel_launch(void* const* d_in, const int* in_sizes, int n_in,
                              void* d_out, int out_size) {
    const float4* x      = (const float4*)d_in[0];
    const float*  M      = (const float*)d_in[1];
    const float*  p_a    = (const float*)d_in[2];
    const float*  p_t    = (const float*)d_in[3];
    const float*  bias_c = (const float*)d_in[4];
    const float*  bias   = (const float*)d_in[5];
    float4* out = (float4*)d_out;

    pixelwise_kernel<<<BLOCKS, THREADS>>>(x, M, p_a, p_t, bias_c, bias, out);
}